// round 14
// baseline (speedup 1.0000x reference)
#include <cuda_runtime.h>
#include <cuda_bf16.h>

#define BB   4
#define CC   64
#define HWD  4096
#define QKD  8
#define NSPL 4
#define NV   33   // Hermitian: v = 0..32

// ---------------- device scratch ----------------
__device__ unsigned       g_Qh[BB*4*HWD];
__device__ unsigned       g_Kh[BB*4*HWD];
__device__ __nv_bfloat16  g_Vh[BB*CC*HWD];
__device__ float g_Opart[NSPL*BB*CC*HWD];
__device__ float g_dpart[NSPL*BB*HWD];
__device__ float g_f1a[BB*64*32*32];   // conv1 partial (ic 0..31) + bias
__device__ float g_f1b[BB*64*32*32];   // conv1 partial (ic 32..63)
__device__ float g_f2[BB*128];
__device__ int   g_branch[BB];
__device__ float g_sobel[BB*HWD];
__device__ float g_hsv[BB*HWD];
__device__ float g_hist[BB*HWD];
__device__ float g_fre[BB*CC*NV*64];   // [b][c][v][r]
__device__ float g_fim[BB*CC*NV*64];
__device__ float g_fftmag[BB*CC*HWD];
__device__ int   g_cnt;    // conv2 completion counter (reset by attn_finish)
__device__ int   g_flag;   // branch-ready flag     (reset by attn_finish)

__device__ const int c_branch_tab[25] =
    {0,0,0,0,0,0,1,1,0,0,0,0,0,0,3,1,1,2,3,0,0,3,3,3,3};

__device__ __forceinline__ float sigmoidf_(float z){ return 1.0f/(1.0f+__expf(-z)); }
__device__ __forceinline__ unsigned pack_bf16x2(float hi, float lo){
    unsigned r; asm("cvt.rn.bf16x2.f32 %0, %1, %2;" : "=r"(r) : "f"(hi), "f"(lo)); return r;
}
__device__ __forceinline__ float ex2_(float v){
    float r; asm("ex2.approx.f32 %0, %1;" : "=f"(r) : "f"(v)); return r;
}
__device__ __forceinline__ void cp16(float* smem_dst, const float* gmem_src){
    unsigned sd = (unsigned)__cvta_generic_to_shared(smem_dst);
    asm volatile("cp.async.cg.shared.global [%0], [%1], 16;" :: "r"(sd), "l"(gmem_src));
}
#define CP_COMMIT()  asm volatile("cp.async.commit_group;")
#define CP_WAIT1()   asm volatile("cp.async.wait_group 1;")
#define CP_WAIT0()   asm volatile("cp.async.wait_group 0;")

// =====================================================================
// PHASE 1: conv1 ic-split (0..511) || qkv (512..767) || fftA (768..1023).
// 256 thr, dyn smem 21504 B. Single wave.
// =====================================================================
__global__ void __launch_bounds__(256) phase1_kernel(const float* __restrict__ x,
    const float* __restrict__ wq, const float* __restrict__ bq,
    const float* __restrict__ wk, const float* __restrict__ bk,
    const float* __restrict__ wv, const float* __restrict__ bv,
    const float* __restrict__ c1w, const float* __restrict__ c1b){
    extern __shared__ float smf[];
    const int blk = blockIdx.x, t = threadIdx.x;

    if (blk < 512){
        // ---- conv1 partial: (ih ic-half, ocg of 2 oc, yh, b); cp.async dbl-buffered
        const int ih = blk & 1, ocg = (blk>>1) & 31, yh = (blk>>6)&1, b = blk>>7;
        const int ic0 = ih*32;
        float* buf0 = smf;          // 2112
        float* buf1 = smf + 2112;   // 2112
        float* ws   = smf + 4224;   // 576 (2 oc x 32 ic x 9)
        for (int i=t;i<576;i+=256){
            int ol = i/288, j = i - ol*288;
            ws[i] = c1w[(ocg*2+ol)*576 + ic0*9 + j];
        }
        if (yh==0) for (int i=t;i<64;i+=256){ buf0[i]=0.f; buf1[i]=0.f; }
        const int ldN   = yh ? 2112 : 2048;
        const int srcOf = yh ? 31*64 : 0;
        const int dstOf = yh ? 0 : 64;
        float* bufs[2] = {buf0, buf1};
        {
            const float* src = x + (((size_t)b*64+ic0)<<12) + srcOf;
            float* dst = buf0 + dstOf;
            for (int i=4*t;i<ldN;i+=1024) cp16(dst+i, src+i);
            CP_COMMIT();
        }
        float acc[2][2] = {{0.f,0.f},{0.f,0.f}};
        const int px = t&31;
        for (int it=0; it<32; ++it){
            if (it<31){
                const float* src = x + (((size_t)b*64+ic0+it+1)<<12) + srcOf;
                float* dst = bufs[(it+1)&1] + dstOf;
                for (int i=4*t;i<ldN;i+=1024) cp16(dst+i, src+i);
                CP_COMMIT();
                CP_WAIT1();
            } else {
                CP_WAIT0();
            }
            __syncthreads();
            const float* xs = bufs[it&1];
            const float* wp0 = ws + it*9;
            const float* wp1 = ws + 288 + it*9;
            #pragma unroll
            for (int pi=0;pi<2;pi++){
                int py = (t>>5) + pi*8;
                int r0 = py*2, ix0 = px*2 - 1;
                float v[9];
                #pragma unroll
                for (int ky=0;ky<3;ky++)
                    #pragma unroll
                    for (int kx=0;kx<3;kx++){
                        int ix = ix0+kx;
                        v[ky*3+kx] = (ix>=0&&ix<64)? xs[(r0+ky)*64 + ix] : 0.f;
                    }
                float s0=0.f, s1=0.f;
                #pragma unroll
                for (int k=0;k<9;k++){ s0 += v[k]*wp0[k]; s1 += v[k]*wp1[k]; }
                acc[pi][0]+=s0; acc[pi][1]+=s1;
            }
            __syncthreads();
        }
        float* dstf = ih ? g_f1b : g_f1a;
        #pragma unroll
        for (int ol=0;ol<2;ol++){
            int oc = ocg*2+ol;
            float bvl = ih ? 0.f : c1b[oc];   // bias in half a only; NO relu here
            #pragma unroll
            for (int pi=0;pi<2;pi++){
                int oy = yh*16 + (t>>5) + pi*8;
                dstf[(((b*64)+oc)<<10) + (oy<<5) + px] = acc[pi][ol]+bvl;
            }
        }
    } else if (blk < 768){
        // ---- qkv: 64-n tiles, 4 quarters (16 V ch each; q0 +Q, q1 +K); direct LDG
        float* wqt = smf;            // 512
        float* wkt = smf + 512;      // 512
        float* wvt = smf + 1024;     // 4096
        const int e = blk - 512;
        const int ntile = e & 63, b = e>>6;
        const int n0 = ntile*64;
        for (int i=t;i<512;i+=256){ int o=i>>6,c=i&63; wqt[c*8+o]=wq[i]; wkt[c*8+o]=wk[i]; }
        for (int i=t;i<4096;i+=256){ int o=i>>6,c=i&63; wvt[c*64+o]=wv[i]; }
        __syncthreads();
        const int qt = t>>6, nl = t&63;
        const int n = n0 + nl;
        float av[16], aqk[8];
        #pragma unroll
        for (int o=0;o<16;o++) av[o]=bv[qt*16+o];
        const float* bqk = (qt==1)? bk : bq;
        #pragma unroll
        for (int o=0;o<8;o++) aqk[o]=bqk[o];
        const float* wqkt = (qt==1)? wkt : wqt;
        const float* xb = x + (size_t)b*CC*HWD + n;
        #pragma unroll 4
        for (int c=0;c<64;c++){
            float xc = xb[(size_t)c*HWD];
            const float4* wv4 = (const float4*)(wvt + c*64 + qt*16);
            #pragma unroll
            for (int j=0;j<4;j++){
                float4 v = wv4[j];
                av[4*j+0]+=v.x*xc; av[4*j+1]+=v.y*xc; av[4*j+2]+=v.z*xc; av[4*j+3]+=v.w*xc;
            }
            if (qt < 2){
                const float4* wq4 = (const float4*)(wqkt + c*8);
                #pragma unroll
                for (int j=0;j<2;j++){
                    float4 q4=wq4[j];
                    aqk[4*j+0]+=q4.x*xc; aqk[4*j+1]+=q4.y*xc; aqk[4*j+2]+=q4.z*xc; aqk[4*j+3]+=q4.w*xc;
                }
            }
        }
        #pragma unroll
        for (int o=0;o<16;o++)
            g_Vh[((size_t)((b<<6)+qt*16+o))*HWD + n] = __float2bfloat16(av[o]);
        if (qt < 2){
            const float f = (qt==1)? 1.0f : (0.35355339059327373f * 1.4426950408889634f);
            unsigned* dst = (qt==1)? g_Kh : g_Qh;
            #pragma unroll
            for (int dp=0;dp<4;dp++)
                dst[((b<<2)+dp)*HWD + n] = pack_bf16x2(aqk[2*dp+1]*f, aqk[2*dp]*f);
        }
    } else {
        // ---- fftA: row DFT (ungated, Hermitian v=0..32), 64 rows per block
        float* xs = smf;   // [64][65] = 4160 floats = 16640 B
        const int e = blk - 768;
        const int c = e&63, b = e>>6;
        const float* xp = x + ((size_t)(((b<<6)+c))<<12);
        for (int i=t;i<4096;i+=256){
            int r=i>>6, j=i&63;
            xs[r*65+j] = xp[i];
        }
        __syncthreads();
        const size_t base = (size_t)((b<<6)+c)*NV*64;
        for (int i=t;i<64*NV;i+=256){
            int r = i/NV, v = i - r*NV;
            float st, ct;
            __sincosf(-6.283185307179586f*(float)v*(1.0f/64.0f), &st, &ct);
            float cv=1.f, sv=0.f, cr=0.f, ci=0.f;
            const float* row = xs + r*65;
            #pragma unroll 4
            for (int j=0;j<64;j++){
                float xv = row[j];
                cr += xv*cv; ci += xv*sv;
                float cn = cv*ct - sv*st;
                sv = sv*ct + cv*st;
                cv = cn;
                if ((j&15)==15){
                    float nrm = __frsqrt_rn(cv*cv + sv*sv);
                    cv *= nrm; sv *= nrm;
                }
            }
            g_fre[base + v*64 + r] = cr;
            g_fim[base + v*64 + r] = ci;
        }
    }
}

// =====================================================================
// PHASE 2: conv2+fc (0..511) || attention (512..1535) || spatial3
// (1536..1663) || fftB gated on flag (1664..2175). 128 thr, 19584 B.
// =====================================================================
__global__ void __launch_bounds__(128) phase2_kernel(const float* __restrict__ x,
    const float* __restrict__ c2w, const float* __restrict__ c2b,
    const float* __restrict__ fcw, const float* __restrict__ fcb){
    extern __shared__ char sm8[];
    const int blk = blockIdx.x, t = threadIdx.x;

    if (blk < 512){
        // ---- conv2 over relu(f1a+f1b); cp.async double-buffered; last block: fc
        float* bufa0 = (float*)sm8;     // 1024
        float* bufa1 = bufa0 + 1024;    // 1024
        float* bufb0 = bufa1 + 1024;    // 1024
        float* bufb1 = bufb0 + 1024;    // 1024
        float* ws    = bufb1 + 1024;    // 576
        float* red   = ws + 576;        // 128
        const int oc = blk & 127, b = blk>>7;
        for (int i=t;i<576;i+=128) ws[i]=c2w[oc*576+i];
        float* bufsa[2] = {bufa0, bufa1};
        float* bufsb[2] = {bufb0, bufb1};
        {
            const float* srca = g_f1a + (((size_t)b*64)<<10);
            const float* srcb = g_f1b + (((size_t)b*64)<<10);
            for (int i=4*t;i<1024;i+=512){ cp16(bufa0+i, srca+i); cp16(bufb0+i, srcb+i); }
            CP_COMMIT();
        }
        float acc0=0.f, acc1=0.f;
        const int ox = t&15;
        for (int ic=0;ic<64;++ic){
            if (ic<63){
                const float* srca = g_f1a + (((size_t)b*64+ic+1)<<10);
                const float* srcb = g_f1b + (((size_t)b*64+ic+1)<<10);
                float* da = bufsa[(ic+1)&1];
                float* db = bufsb[(ic+1)&1];
                for (int i=4*t;i<1024;i+=512){ cp16(da+i, srca+i); cp16(db+i, srcb+i); }
                CP_COMMIT();
                CP_WAIT1();
            } else {
                CP_WAIT0();
            }
            __syncthreads();
            const float* xa = bufsa[ic&1];
            const float* xbuf = bufsb[ic&1];
            const float* wp = ws + ic*9;
            #pragma unroll
            for (int pi=0;pi<2;pi++){
                int oy = (t>>4) + pi*8;
                int iy0=2*oy-1, ix0=2*ox-1;
                float a=0.f;
                #pragma unroll
                for (int ky=0;ky<3;ky++)
                    #pragma unroll
                    for (int kx=0;kx<3;kx++){
                        int iy=iy0+ky, ix=ix0+kx;
                        float xv = 0.f;
                        if (iy>=0&&iy<32&&ix>=0&&ix<32){
                            int idx = (iy<<5)+ix;
                            xv = fmaxf(xa[idx]+xbuf[idx], 0.f);
                        }
                        a += xv*wp[ky*3+kx];
                    }
                if (pi==0) acc0+=a; else acc1+=a;
            }
            __syncthreads();
        }
        float bvl = c2b[oc];
        float r0 = acc0+bvl; r0 = r0>0.f? r0:0.f;
        float r1 = acc1+bvl; r1 = r1>0.f? r1:0.f;
        red[t]=r0+r1; __syncthreads();
        for (int s=64;s>0;s>>=1){ if(t<s) red[t]+=red[t+s]; __syncthreads(); }
        __shared__ int amlast;
        if (t==0){
            g_f2[b*128+oc] = red[0]*(1.0f/256.0f);
            __threadfence();
            int old = atomicAdd(&g_cnt, 1);
            amlast = (old == 511);
        }
        __syncthreads();
        if (amlast){
            int wid = t>>5, lane = t&31;
            if (wid < BB){
                float v = -1e30f; int idx = lane;
                if (lane < 25){
                    float s = fcb[lane];
                    const float* f2   = g_f2 + wid*128;
                    const float* wrow = fcw  + lane*128;
                    #pragma unroll 4
                    for (int k=0;k<128;k++) s += f2[k]*wrow[k];
                    v = s;
                }
                #pragma unroll
                for (int off=16;off>0;off>>=1){
                    float ov = __shfl_down_sync(0xffffffffu, v,   off);
                    int   oi = __shfl_down_sync(0xffffffffu, idx, off);
                    if (ov > v || (ov==v && oi<idx)){ v=ov; idx=oi; }
                }
                if (lane==0) g_branch[wid] = c_branch_tab[idx];
            }
            __syncthreads();
            if (t==0){ __threadfence(); atomicExch(&g_flag, 1); }
        }
    } else if (blk < 1536){
        // ---- tensor-core flash attention, split-KV x4
        unsigned* Ksu = (unsigned*)sm8;               // 4*136 u32
        unsigned* Vsu = (unsigned*)(sm8 + 2176);      // 64*68 u32
        float*    Osm = (float*)(sm8 + 2176);
        const int e = blk - 512;
        const int lane = t&31, w = t>>5;
        const int g = lane>>2, l = lane&3;
        const int qt = e & 63, spl = (e>>6)&3, b = e>>8;
        const int n0 = qt*64;
        const int qw = w*16;

        unsigned qa0 = g_Qh[((b<<2)+l)*HWD + n0 + qw + g];
        unsigned qa1 = g_Qh[((b<<2)+l)*HWD + n0 + qw + g + 8];
        const unsigned zz = 0u;

        float o[32];
        #pragma unroll
        for (int i=0;i<32;i++) o[i]=0.f;
        float d0=0.f, d1=0.f;

        const int kt0 = spl*(32/NSPL), kt1 = kt0 + (32/NSPL);
        for (int kt=kt0;kt<kt1;kt++){
            const int m0 = kt<<7;
            __syncthreads();
            {
                int dp = t>>5, j = t&31;
                ((uint4*)(Ksu + dp*136))[j] =
                    ((const uint4*)(g_Kh + ((b<<2)+dp)*HWD + m0))[j];
            }
            for (int i=t;i<1024;i+=128){
                int r = i>>4, j = i&15;
                ((uint4*)(Vsu + r*68))[j] =
                    ((const uint4*)(g_Vh + ((size_t)((b<<6)+r))*HWD + m0))[j];
            }
            __syncthreads();

            #pragma unroll 2
            for (int mc=0;mc<8;mc++){
                const int m16 = mc<<4;
                float s0,s1,s2,s3,s4,s5,s6,s7;
                unsigned kb0 = Ksu[l*136 + m16 + g];
                unsigned kb1 = Ksu[l*136 + m16 + 8 + g];
                asm("mma.sync.aligned.m16n8k16.row.col.f32.bf16.bf16.f32 "
                    "{%0,%1,%2,%3},{%4,%5,%6,%7},{%8,%9},{%10,%11,%12,%13};"
                    : "=f"(s0),"=f"(s1),"=f"(s2),"=f"(s3)
                    : "r"(qa0),"r"(qa1),"r"(zz),"r"(zz), "r"(kb0),"r"(zz),
                      "f"(0.f),"f"(0.f),"f"(0.f),"f"(0.f));
                asm("mma.sync.aligned.m16n8k16.row.col.f32.bf16.bf16.f32 "
                    "{%0,%1,%2,%3},{%4,%5,%6,%7},{%8,%9},{%10,%11,%12,%13};"
                    : "=f"(s4),"=f"(s5),"=f"(s6),"=f"(s7)
                    : "r"(qa0),"r"(qa1),"r"(zz),"r"(zz), "r"(kb1),"r"(zz),
                      "f"(0.f),"f"(0.f),"f"(0.f),"f"(0.f));
                s0=ex2_(s0); s1=ex2_(s1); s2=ex2_(s2); s3=ex2_(s3);
                s4=ex2_(s4); s5=ex2_(s5); s6=ex2_(s6); s7=ex2_(s7);
                d0 += (s0+s1)+(s4+s5);
                d1 += (s2+s3)+(s6+s7);
                unsigned p0 = pack_bf16x2(s1,s0);
                unsigned p1 = pack_bf16x2(s3,s2);
                unsigned p2 = pack_bf16x2(s5,s4);
                unsigned p3 = pack_bf16x2(s7,s6);
                const int vbase = (m16>>1) + l;
                #pragma unroll
                for (int ct=0;ct<8;ct++){
                    unsigned vb0 = Vsu[(ct*8+g)*68 + vbase];
                    unsigned vb1 = Vsu[(ct*8+g)*68 + vbase + 4];
                    asm("mma.sync.aligned.m16n8k16.row.col.f32.bf16.bf16.f32 "
                        "{%0,%1,%2,%3},{%4,%5,%6,%7},{%8,%9},{%0,%1,%2,%3};"
                        : "+f"(o[ct*4+0]),"+f"(o[ct*4+1]),"+f"(o[ct*4+2]),"+f"(o[ct*4+3])
                        : "r"(p0),"r"(p1),"r"(p2),"r"(p3), "r"(vb0),"r"(vb1));
                }
            }
        }
        d0 += __shfl_xor_sync(0xffffffffu, d0, 1);
        d0 += __shfl_xor_sync(0xffffffffu, d0, 2);
        d1 += __shfl_xor_sync(0xffffffffu, d1, 1);
        d1 += __shfl_xor_sync(0xffffffffu, d1, 2);
        if (l == 0){
            g_dpart[((spl*BB + b)<<12) + n0 + qw + g    ] = d0;
            g_dpart[((spl*BB + b)<<12) + n0 + qw + g + 8] = d1;
        }

        __syncthreads();
        #pragma unroll
        for (int ct=0;ct<8;ct++){
            int c0 = ct*8 + 2*l;
            Osm[ c0   *68 + qw + g    ] = o[ct*4+0];
            Osm[(c0+1)*68 + qw + g    ] = o[ct*4+1];
            Osm[ c0   *68 + qw + g + 8] = o[ct*4+2];
            Osm[(c0+1)*68 + qw + g + 8] = o[ct*4+3];
        }
        __syncthreads();
        float* op = g_Opart + ((size_t)(spl*BB + b)*CC<<12) + n0;
        for (int i=t;i<4096;i+=128){
            int c = i>>6, q = i&63;
            op[((size_t)c<<12) + q] = Osm[c*68+q];
        }
    } else if (blk < 1664){
        // ---- sobel/hsv/hist maps (ungated), 2 rows per block
        float (*xs)[4][64] = (float (*)[4][64])sm8;
        const int e = blk - 1536;
        const int seg = e & 31, b = e>>5;
        const int y0 = seg*2;
        const int ty = t>>6, tx = t&63;
        const int y = y0 + ty;
        const float* xb = x + ((size_t)b<<18);
        float ssum=0.f, csum=0.f, mx=-1e30f, mn=1e30f;
        #pragma unroll
        for (int i=t;i<256;i+=128){
            int r=i>>6, xx=i&63, yy=y0-1+r;
            xs[0][r][xx] = (yy>=0&&yy<64)? xb[(yy<<6)+xx] : 0.f;
        }
        __syncthreads();
        for (int c=0;c<64;c++){
            if (c+1<64){
                const float* xp = xb + ((size_t)(c+1)<<12);
                #pragma unroll
                for (int i=t;i<256;i+=128){
                    int r=i>>6, xx=i&63, yy=y0-1+r;
                    xs[(c+1)&1][r][xx] = (yy>=0&&yy<64)? xp[(yy<<6)+xx] : 0.f;
                }
            }
            const float (*cur)[64] = xs[c&1];
            float v[3][3];
            #pragma unroll
            for (int dy=0;dy<3;dy++)
                #pragma unroll
                for (int dx=-1;dx<=1;dx++){
                    int xx=tx+dx;
                    v[dy][dx+1] = (xx>=0&&xx<64)? cur[ty+dy][xx] : 0.f;
                }
            float gx = (v[0][2]+2.f*v[1][2]+v[2][2]) - (v[0][0]+2.f*v[1][0]+v[2][0]);
            float gy = (v[2][0]+2.f*v[2][1]+v[2][2]) - (v[0][0]+2.f*v[0][1]+v[0][2]);
            ssum += sqrtf(gx*gx+gy*gy);
            float ctr = v[1][1];
            csum += ctr; mx = fmaxf(mx,ctr); mn = fminf(mn,ctr);
            __syncthreads();
        }
        int id = (b<<12) + (y<<6) + tx;
        g_sobel[id] = sigmoidf_(ssum*(1.0f/64.0f));
        g_hsv[id]   = (mx-mn+1e-6f)/(mx+1e-6f);
        g_hist[id]  = sigmoidf_(csum*(1.0f/64.0f));
    } else {
        // ---- fftB: wait for branch flag, then col DFT + mag (gated)
        const int e = blk - 1664;
        const int uh = e&1, c = (e>>1)&63, b = e>>7;
        if (t==0){
            while (atomicAdd(&g_flag, 0) == 0) __nanosleep(200);
        }
        __syncthreads();
        __threadfence();
        volatile int* vbr = g_branch;
        if (vbr[b] != 3) return;
        float* Rs = (float*)sm8;            // NV*65
        float* Is = Rs + NV*65;
        const size_t base = (size_t)((b<<6)+c)*NV*64;
        for (int i=t;i<NV*64;i+=128){
            int v=i>>6, r=i&63;
            Rs[v*65+r] = g_fre[base+i];
            Is[v*65+r] = g_fim[base+i];
        }
        __syncthreads();
        float* outp = g_fftmag + ((size_t)(((b<<6)+c))<<12);
        for (int i=t;i<32*NV;i+=128){
            int u = uh*32 + i/NV, v = i - (i/NV)*NV;
            float st, ct;
            __sincosf(-6.283185307179586f*(float)u*(1.0f/64.0f), &st, &ct);
            float cu=1.f, su=0.f, fr=0.f, fi=0.f;
            const float* Rp = Rs + v*65;
            const float* Ip = Is + v*65;
            #pragma unroll 4
            for (int r=0;r<64;r++){
                float a=Rp[r], bm=Ip[r];
                fr += a*cu - bm*su;
                fi += a*su + bm*cu;
                float cn = cu*ct - su*st;
                su = su*ct + cu*st;
                cu = cn;
                if ((r&15)==15){
                    float nrm = __frsqrt_rn(cu*cu + su*su);
                    cu *= nrm; su *= nrm;
                }
            }
            float mag = sqrtf(fr*fr+fi*fi);
            int su_=(u+32)&63, sv_=(v+32)&63;
            outp[(su_<<6)+sv_] = mag;
            int u2=(64-u)&63, v2=(64-v)&63;
            int su2=(u2+32)&63, sv2=(v2+32)&63;
            outp[(su2<<6)+sv2] = mag;
        }
    }
}

// ---------------- combine split partials + routed spatial epilogue ----------------
// grid (256, 4): blk.x = (ntile 0..63, cgroup 0..3); 16 channels x 64 q per block
__global__ void __launch_bounds__(256) attn_finish(const float* __restrict__ x,
                                                   const float* __restrict__ swp,
                                                   float* __restrict__ out){
    __shared__ float scl[64];
    const int t = threadIdx.x;
    const int bx = blockIdx.x;
    const int ntile = bx & 63, cg = bx >> 6;
    const int b = blockIdx.y, n0 = ntile*64;
    if (bx==0 && b==0 && t==0){ g_cnt = 0; g_flag = 0; }  // reset for next replay
    if (t < 64){
        float d = 0.f;
        #pragma unroll
        for (int s=0;s<NSPL;s++) d += g_dpart[((s*BB + b)<<12) + n0 + t];
        const int br = g_branch[b];
        const int id = (b<<12) + n0 + t;
        float v;
        if      (br==0) v = g_sobel[id];
        else if (br==1) v = g_hsv[id];
        else if (br==2) v = g_hist[id];
        else {
            float s=0.f;
            const float* mp = g_fftmag + ((size_t)b<<18) + n0 + t;
            #pragma unroll 4
            for (int c=0;c<64;c++) s += mp[(size_t)c<<12];
            v = sigmoidf_(s*(1.0f/64.0f));
        }
        scl[t] = swp[0]*v/d;
    }
    __syncthreads();
    for (int i=t;i<1024;i+=256){
        int c = cg*16 + (i>>6), q = i&63;
        size_t po = ((size_t)(b*CC + c)<<12) + n0 + q;
        float osum = 0.f;
        #pragma unroll
        for (int s=0;s<NSPL;s++) osum += g_Opart[((size_t)(s*BB*CC)<<12) + po];
        out[po] = osum*scl[q] + x[po];
    }
}

// ---------------- launch ----------------
extern "C" void kernel_launch(void* const* d_in, const int* in_sizes, int n_in,
                              void* d_out, int out_size){
    const float* x    = (const float*)d_in[0];
    const float* wq   = (const float*)d_in[1];
    const float* bq   = (const float*)d_in[2];
    const float* wk   = (const float*)d_in[3];
    const float* bk   = (const float*)d_in[4];
    const float* wv   = (const float*)d_in[5];
    const float* bv   = (const float*)d_in[6];
    const float* c1w  = (const float*)d_in[7];
    const float* c1b  = (const float*)d_in[8];
    const float* c2w  = (const float*)d_in[9];
    const float* c2b  = (const float*)d_in[10];
    const float* fcw  = (const float*)d_in[11];
    const float* fcb  = (const float*)d_in[12];
    const float* swp  = (const float*)d_in[13];
    float* out = (float*)d_out;

    cudaFuncSetAttribute(phase1_kernel, cudaFuncAttributeMaxDynamicSharedMemorySize, 21504);

    phase1_kernel  <<<1024, 256, 21504>>>(x, wq,bq, wk,bk, wv,bv, c1w, c1b);
    phase2_kernel  <<<2176, 128, 19584>>>(x, c2w, c2b, fcw, fcb);
    attn_finish    <<<dim3(256,4), 256>>>(x, swp, out);
}

// round 16
// speedup vs baseline: 1.1573x; 1.1573x over previous
#include <cuda_runtime.h>
#include <cuda_bf16.h>

#define BB   4
#define CC   64
#define HWD  4096
#define QKD  8
#define NSPL 4
#define NV   33   // Hermitian: v = 0..32

// ---------------- device scratch ----------------
__device__ unsigned       g_Qh[BB*4*HWD];
__device__ unsigned       g_Kh[BB*4*HWD];
__device__ __nv_bfloat16  g_Vh[BB*CC*HWD];
__device__ float g_Opart[NSPL*BB*CC*HWD];
__device__ float g_dpart[NSPL*BB*HWD];
__device__ float g_f1a[BB*64*32*32];   // conv1 partial (ic 0..31) + bias
__device__ float g_f1b[BB*64*32*32];   // conv1 partial (ic 32..63)
__device__ float g_f1 [BB*64*32*32];   // merged relu(a+b)
__device__ float g_f2[BB*128];
__device__ int   g_branch[BB];
__device__ float g_sobel[BB*HWD];
__device__ float g_hsv[BB*HWD];
__device__ float g_hist[BB*HWD];
__device__ float g_fre[BB*CC*NV*64];   // [b][c][v][r]
__device__ float g_fim[BB*CC*NV*64];
__device__ float g_fftmag[BB*CC*HWD];
__device__ int   g_cnt;     // conv2 completion counter
__device__ int   g_flag;    // branch-ready flag
__device__ int   g_m_cnt;   // merge completion counter
__device__ int   g_m_flag;  // merge-done flag

__device__ const int c_branch_tab[25] =
    {0,0,0,0,0,0,1,1,0,0,0,0,0,0,3,1,1,2,3,0,0,3,3,3,3};

__device__ __forceinline__ float sigmoidf_(float z){ return 1.0f/(1.0f+__expf(-z)); }
__device__ __forceinline__ unsigned pack_bf16x2(float hi, float lo){
    unsigned r; asm("cvt.rn.bf16x2.f32 %0, %1, %2;" : "=r"(r) : "f"(hi), "f"(lo)); return r;
}
__device__ __forceinline__ float ex2_(float v){
    float r; asm("ex2.approx.f32 %0, %1;" : "=f"(r) : "f"(v)); return r;
}
__device__ __forceinline__ void cp16(float* smem_dst, const float* gmem_src){
    unsigned sd = (unsigned)__cvta_generic_to_shared(smem_dst);
    asm volatile("cp.async.cg.shared.global [%0], [%1], 16;" :: "r"(sd), "l"(gmem_src));
}
#define CP_COMMIT()  asm volatile("cp.async.commit_group;")
#define CP_WAIT1()   asm volatile("cp.async.wait_group 1;")
#define CP_WAIT0()   asm volatile("cp.async.wait_group 0;")

// =====================================================================
// PHASE 1: conv1 ic-split (0..511) || qkv (512..767) || fftA (768..1023).
// 256 thr, dyn smem 21504 B. Single wave.
// =====================================================================
__global__ void __launch_bounds__(256) phase1_kernel(const float* __restrict__ x,
    const float* __restrict__ wq, const float* __restrict__ bq,
    const float* __restrict__ wk, const float* __restrict__ bk,
    const float* __restrict__ wv, const float* __restrict__ bv,
    const float* __restrict__ c1w, const float* __restrict__ c1b){
    extern __shared__ float smf[];
    const int blk = blockIdx.x, t = threadIdx.x;

    if (blk < 512){
        // ---- conv1 partial: (ih ic-half, ocg of 2 oc, yh, b); cp.async dbl-buffered
        const int ih = blk & 1, ocg = (blk>>1) & 31, yh = (blk>>6)&1, b = blk>>7;
        const int ic0 = ih*32;
        float* buf0 = smf;          // 2112
        float* buf1 = smf + 2112;   // 2112
        float* ws   = smf + 4224;   // 576 (2 oc x 32 ic x 9)
        for (int i=t;i<576;i+=256){
            int ol = i/288, j = i - ol*288;
            ws[i] = c1w[(ocg*2+ol)*576 + ic0*9 + j];
        }
        if (yh==0) for (int i=t;i<64;i+=256){ buf0[i]=0.f; buf1[i]=0.f; }
        const int ldN   = yh ? 2112 : 2048;
        const int srcOf = yh ? 31*64 : 0;
        const int dstOf = yh ? 0 : 64;
        float* bufs[2] = {buf0, buf1};
        {
            const float* src = x + (((size_t)b*64+ic0)<<12) + srcOf;
            float* dst = buf0 + dstOf;
            for (int i=4*t;i<ldN;i+=1024) cp16(dst+i, src+i);
            CP_COMMIT();
        }
        float acc[2][2] = {{0.f,0.f},{0.f,0.f}};
        const int px = t&31;
        for (int it=0; it<32; ++it){
            if (it<31){
                const float* src = x + (((size_t)b*64+ic0+it+1)<<12) + srcOf;
                float* dst = bufs[(it+1)&1] + dstOf;
                for (int i=4*t;i<ldN;i+=1024) cp16(dst+i, src+i);
                CP_COMMIT();
                CP_WAIT1();
            } else {
                CP_WAIT0();
            }
            __syncthreads();
            const float* xs = bufs[it&1];
            const float* wp0 = ws + it*9;
            const float* wp1 = ws + 288 + it*9;
            #pragma unroll
            for (int pi=0;pi<2;pi++){
                int py = (t>>5) + pi*8;
                int r0 = py*2, ix0 = px*2 - 1;
                float v[9];
                #pragma unroll
                for (int ky=0;ky<3;ky++)
                    #pragma unroll
                    for (int kx=0;kx<3;kx++){
                        int ix = ix0+kx;
                        v[ky*3+kx] = (ix>=0&&ix<64)? xs[(r0+ky)*64 + ix] : 0.f;
                    }
                float s0=0.f, s1=0.f;
                #pragma unroll
                for (int k=0;k<9;k++){ s0 += v[k]*wp0[k]; s1 += v[k]*wp1[k]; }
                acc[pi][0]+=s0; acc[pi][1]+=s1;
            }
            __syncthreads();
        }
        float* dstf = ih ? g_f1b : g_f1a;
        #pragma unroll
        for (int ol=0;ol<2;ol++){
            int oc = ocg*2+ol;
            float bvl = ih ? 0.f : c1b[oc];   // bias in half a only; NO relu here
            #pragma unroll
            for (int pi=0;pi<2;pi++){
                int oy = yh*16 + (t>>5) + pi*8;
                dstf[(((b*64)+oc)<<10) + (oy<<5) + px] = acc[pi][ol]+bvl;
            }
        }
    } else if (blk < 768){
        // ---- qkv: 64-n tiles, 4 quarters (16 V ch each; q0 +Q, q1 +K); direct LDG
        float* wqt = smf;            // 512
        float* wkt = smf + 512;      // 512
        float* wvt = smf + 1024;     // 4096
        const int e = blk - 512;
        const int ntile = e & 63, b = e>>6;
        const int n0 = ntile*64;
        for (int i=t;i<512;i+=256){ int o=i>>6,c=i&63; wqt[c*8+o]=wq[i]; wkt[c*8+o]=wk[i]; }
        for (int i=t;i<4096;i+=256){ int o=i>>6,c=i&63; wvt[c*64+o]=wv[i]; }
        __syncthreads();
        const int qt = t>>6, nl = t&63;
        const int n = n0 + nl;
        float av[16], aqk[8];
        #pragma unroll
        for (int o=0;o<16;o++) av[o]=bv[qt*16+o];
        const float* bqk = (qt==1)? bk : bq;
        #pragma unroll
        for (int o=0;o<8;o++) aqk[o]=bqk[o];
        const float* wqkt = (qt==1)? wkt : wqt;
        const float* xb = x + (size_t)b*CC*HWD + n;
        #pragma unroll 4
        for (int c=0;c<64;c++){
            float xc = xb[(size_t)c*HWD];
            const float4* wv4 = (const float4*)(wvt + c*64 + qt*16);
            #pragma unroll
            for (int j=0;j<4;j++){
                float4 v = wv4[j];
                av[4*j+0]+=v.x*xc; av[4*j+1]+=v.y*xc; av[4*j+2]+=v.z*xc; av[4*j+3]+=v.w*xc;
            }
            if (qt < 2){
                const float4* wq4 = (const float4*)(wqkt + c*8);
                #pragma unroll
                for (int j=0;j<2;j++){
                    float4 q4=wq4[j];
                    aqk[4*j+0]+=q4.x*xc; aqk[4*j+1]+=q4.y*xc; aqk[4*j+2]+=q4.z*xc; aqk[4*j+3]+=q4.w*xc;
                }
            }
        }
        #pragma unroll
        for (int o=0;o<16;o++)
            g_Vh[((size_t)((b<<6)+qt*16+o))*HWD + n] = __float2bfloat16(av[o]);
        if (qt < 2){
            const float f = (qt==1)? 1.0f : (0.35355339059327373f * 1.4426950408889634f);
            unsigned* dst = (qt==1)? g_Kh : g_Qh;
            #pragma unroll
            for (int dp=0;dp<4;dp++)
                dst[((b<<2)+dp)*HWD + n] = pack_bf16x2(aqk[2*dp+1]*f, aqk[2*dp]*f);
        }
    } else {
        // ---- fftA: row DFT (ungated, Hermitian v=0..32), 64 rows per block
        float* xs = smf;   // [64][65] = 4160 floats = 16640 B
        const int e = blk - 768;
        const int c = e&63, b = e>>6;
        const float* xp = x + ((size_t)(((b<<6)+c))<<12);
        for (int i=t;i<4096;i+=256){
            int r=i>>6, j=i&63;
            xs[r*65+j] = xp[i];
        }
        __syncthreads();
        const size_t base = (size_t)((b<<6)+c)*NV*64;
        for (int i=t;i<64*NV;i+=256){
            int r = i/NV, v = i - r*NV;
            float st, ct;
            __sincosf(-6.283185307179586f*(float)v*(1.0f/64.0f), &st, &ct);
            float cv=1.f, sv=0.f, cr=0.f, ci=0.f;
            const float* row = xs + r*65;
            #pragma unroll 4
            for (int j=0;j<64;j++){
                float xv = row[j];
                cr += xv*cv; ci += xv*sv;
                float cn = cv*ct - sv*st;
                sv = sv*ct + cv*st;
                cv = cn;
                if ((j&15)==15){
                    float nrm = __frsqrt_rn(cv*cv + sv*sv);
                    cv *= nrm; sv *= nrm;
                }
            }
            g_fre[base + v*64 + r] = cr;
            g_fim[base + v*64 + r] = ci;
        }
    }
}

// =====================================================================
// PHASE 2: merge (0..127) || conv2+fc (128..639) || attention (640..1663)
// || spatial3 (1664..1791) || fftB gated (1792..2303). 128 thr, 19584 B.
// =====================================================================
__global__ void __launch_bounds__(128) phase2_kernel(const float* __restrict__ x,
    const float* __restrict__ c2w, const float* __restrict__ c2b,
    const float* __restrict__ fcw, const float* __restrict__ fcb){
    extern __shared__ char sm8[];
    const int blk = blockIdx.x, t = threadIdx.x;

    if (blk < 128){
        // ---- merge: g_f1 = relu(g_f1a + g_f1b); 2048 floats = 512 float4 per block
        const size_t base = (size_t)blk*2048;
        const float4* pa = (const float4*)(g_f1a + base);
        const float4* pb = (const float4*)(g_f1b + base);
        float4*       pm = (float4*)(g_f1 + base);
        #pragma unroll
        for (int i=t;i<512;i+=128){
            float4 a = pa[i], b4 = pb[i], r;
            r.x = fmaxf(a.x+b4.x, 0.f);
            r.y = fmaxf(a.y+b4.y, 0.f);
            r.z = fmaxf(a.z+b4.z, 0.f);
            r.w = fmaxf(a.w+b4.w, 0.f);
            pm[i] = r;
        }
        __syncthreads();
        if (t==0){
            __threadfence();
            if (atomicAdd(&g_m_cnt, 1) == 127) atomicExch(&g_m_flag, 1);
        }
    } else if (blk < 640){
        // ---- conv2 (waits merge); cp.async double-buffered; last block: fc
        if (t==0){
            while (atomicAdd(&g_m_flag, 0) == 0) __nanosleep(100);
        }
        __syncthreads();
        __threadfence();
        float* buf0 = (float*)sm8;   // 1024
        float* buf1 = buf0 + 1024;   // 1024
        float* ws   = buf1 + 1024;   // 576
        float* red  = ws + 576;      // 128
        const int e = blk - 128;
        const int oc = e & 127, b = e>>7;
        for (int i=t;i<576;i+=128) ws[i]=c2w[oc*576+i];
        float* bufs[2] = {buf0, buf1};
        {
            const float* src = g_f1 + (((size_t)b*64)<<10);
            for (int i=4*t;i<1024;i+=512) cp16(buf0+i, src+i);
            CP_COMMIT();
        }
        float acc0=0.f, acc1=0.f;
        const int ox = t&15;
        for (int ic=0;ic<64;++ic){
            if (ic<63){
                const float* src = g_f1 + (((size_t)b*64+ic+1)<<10);
                float* dst = bufs[(ic+1)&1];
                for (int i=4*t;i<1024;i+=512) cp16(dst+i, src+i);
                CP_COMMIT();
                CP_WAIT1();
            } else {
                CP_WAIT0();
            }
            __syncthreads();
            const float* xs = bufs[ic&1];
            const float* wp = ws + ic*9;
            #pragma unroll
            for (int pi=0;pi<2;pi++){
                int oy = (t>>4) + pi*8;
                int iy0=2*oy-1, ix0=2*ox-1;
                float a=0.f;
                #pragma unroll
                for (int ky=0;ky<3;ky++)
                    #pragma unroll
                    for (int kx=0;kx<3;kx++){
                        int iy=iy0+ky, ix=ix0+kx;
                        float xv = (iy>=0&&iy<32&&ix>=0&&ix<32)? xs[(iy<<5)+ix] : 0.0f;
                        a += xv*wp[ky*3+kx];
                    }
                if (pi==0) acc0+=a; else acc1+=a;
            }
            __syncthreads();
        }
        float bvl = c2b[oc];
        float r0 = acc0+bvl; r0 = r0>0.f? r0:0.f;
        float r1 = acc1+bvl; r1 = r1>0.f? r1:0.f;
        red[t]=r0+r1; __syncthreads();
        for (int s=64;s>0;s>>=1){ if(t<s) red[t]+=red[t+s]; __syncthreads(); }
        __shared__ int amlast;
        if (t==0){
            g_f2[b*128+oc] = red[0]*(1.0f/256.0f);
            __threadfence();
            int old = atomicAdd(&g_cnt, 1);
            amlast = (old == 511);
        }
        __syncthreads();
        if (amlast){
            int wid = t>>5, lane = t&31;
            if (wid < BB){
                float v = -1e30f; int idx = lane;
                if (lane < 25){
                    float s = fcb[lane];
                    const float* f2   = g_f2 + wid*128;
                    const float* wrow = fcw  + lane*128;
                    #pragma unroll 4
                    for (int k=0;k<128;k++) s += f2[k]*wrow[k];
                    v = s;
                }
                #pragma unroll
                for (int off=16;off>0;off>>=1){
                    float ov = __shfl_down_sync(0xffffffffu, v,   off);
                    int   oi = __shfl_down_sync(0xffffffffu, idx, off);
                    if (ov > v || (ov==v && oi<idx)){ v=ov; idx=oi; }
                }
                if (lane==0) g_branch[wid] = c_branch_tab[idx];
            }
            __syncthreads();
            if (t==0){ __threadfence(); atomicExch(&g_flag, 1); }
        }
    } else if (blk < 1664){
        // ---- tensor-core flash attention, split-KV x4
        unsigned* Ksu = (unsigned*)sm8;               // 4*136 u32
        unsigned* Vsu = (unsigned*)(sm8 + 2176);      // 64*68 u32
        float*    Osm = (float*)(sm8 + 2176);
        const int e = blk - 640;
        const int lane = t&31, w = t>>5;
        const int g = lane>>2, l = lane&3;
        const int qt = e & 63, spl = (e>>6)&3, b = e>>8;
        const int n0 = qt*64;
        const int qw = w*16;

        unsigned qa0 = g_Qh[((b<<2)+l)*HWD + n0 + qw + g];
        unsigned qa1 = g_Qh[((b<<2)+l)*HWD + n0 + qw + g + 8];
        const unsigned zz = 0u;

        float o[32];
        #pragma unroll
        for (int i=0;i<32;i++) o[i]=0.f;
        float d0=0.f, d1=0.f;

        const int kt0 = spl*(32/NSPL), kt1 = kt0 + (32/NSPL);
        for (int kt=kt0;kt<kt1;kt++){
            const int m0 = kt<<7;
            __syncthreads();
            {
                int dp = t>>5, j = t&31;
                ((uint4*)(Ksu + dp*136))[j] =
                    ((const uint4*)(g_Kh + ((b<<2)+dp)*HWD + m0))[j];
            }
            for (int i=t;i<1024;i+=128){
                int r = i>>4, j = i&15;
                ((uint4*)(Vsu + r*68))[j] =
                    ((const uint4*)(g_Vh + ((size_t)((b<<6)+r))*HWD + m0))[j];
            }
            __syncthreads();

            #pragma unroll 2
            for (int mc=0;mc<8;mc++){
                const int m16 = mc<<4;
                float s0,s1,s2,s3,s4,s5,s6,s7;
                unsigned kb0 = Ksu[l*136 + m16 + g];
                unsigned kb1 = Ksu[l*136 + m16 + 8 + g];
                asm("mma.sync.aligned.m16n8k16.row.col.f32.bf16.bf16.f32 "
                    "{%0,%1,%2,%3},{%4,%5,%6,%7},{%8,%9},{%10,%11,%12,%13};"
                    : "=f"(s0),"=f"(s1),"=f"(s2),"=f"(s3)
                    : "r"(qa0),"r"(qa1),"r"(zz),"r"(zz), "r"(kb0),"r"(zz),
                      "f"(0.f),"f"(0.f),"f"(0.f),"f"(0.f));
                asm("mma.sync.aligned.m16n8k16.row.col.f32.bf16.bf16.f32 "
                    "{%0,%1,%2,%3},{%4,%5,%6,%7},{%8,%9},{%10,%11,%12,%13};"
                    : "=f"(s4),"=f"(s5),"=f"(s6),"=f"(s7)
                    : "r"(qa0),"r"(qa1),"r"(zz),"r"(zz), "r"(kb1),"r"(zz),
                      "f"(0.f),"f"(0.f),"f"(0.f),"f"(0.f));
                s0=ex2_(s0); s1=ex2_(s1); s2=ex2_(s2); s3=ex2_(s3);
                s4=ex2_(s4); s5=ex2_(s5); s6=ex2_(s6); s7=ex2_(s7);
                d0 += (s0+s1)+(s4+s5);
                d1 += (s2+s3)+(s6+s7);
                unsigned p0 = pack_bf16x2(s1,s0);
                unsigned p1 = pack_bf16x2(s3,s2);
                unsigned p2 = pack_bf16x2(s5,s4);
                unsigned p3 = pack_bf16x2(s7,s6);
                const int vbase = (m16>>1) + l;
                #pragma unroll
                for (int ct=0;ct<8;ct++){
                    unsigned vb0 = Vsu[(ct*8+g)*68 + vbase];
                    unsigned vb1 = Vsu[(ct*8+g)*68 + vbase + 4];
                    asm("mma.sync.aligned.m16n8k16.row.col.f32.bf16.bf16.f32 "
                        "{%0,%1,%2,%3},{%4,%5,%6,%7},{%8,%9},{%0,%1,%2,%3};"
                        : "+f"(o[ct*4+0]),"+f"(o[ct*4+1]),"+f"(o[ct*4+2]),"+f"(o[ct*4+3])
                        : "r"(p0),"r"(p1),"r"(p2),"r"(p3), "r"(vb0),"r"(vb1));
                }
            }
        }
        d0 += __shfl_xor_sync(0xffffffffu, d0, 1);
        d0 += __shfl_xor_sync(0xffffffffu, d0, 2);
        d1 += __shfl_xor_sync(0xffffffffu, d1, 1);
        d1 += __shfl_xor_sync(0xffffffffu, d1, 2);
        if (l == 0){
            g_dpart[((spl*BB + b)<<12) + n0 + qw + g    ] = d0;
            g_dpart[((spl*BB + b)<<12) + n0 + qw + g + 8] = d1;
        }

        __syncthreads();
        #pragma unroll
        for (int ct=0;ct<8;ct++){
            int c0 = ct*8 + 2*l;
            Osm[ c0   *68 + qw + g    ] = o[ct*4+0];
            Osm[(c0+1)*68 + qw + g    ] = o[ct*4+1];
            Osm[ c0   *68 + qw + g + 8] = o[ct*4+2];
            Osm[(c0+1)*68 + qw + g + 8] = o[ct*4+3];
        }
        __syncthreads();
        float* op = g_Opart + ((size_t)(spl*BB + b)*CC<<12) + n0;
        for (int i=t;i<4096;i+=128){
            int c = i>>6, q = i&63;
            op[((size_t)c<<12) + q] = Osm[c*68+q];
        }
    } else if (blk < 1792){
        // ---- sobel/hsv/hist maps (ungated), 2 rows per block
        float (*xs)[4][64] = (float (*)[4][64])sm8;
        const int e = blk - 1664;
        const int seg = e & 31, b = e>>5;
        const int y0 = seg*2;
        const int ty = t>>6, tx = t&63;
        const int y = y0 + ty;
        const float* xb = x + ((size_t)b<<18);
        float ssum=0.f, csum=0.f, mx=-1e30f, mn=1e30f;
        #pragma unroll
        for (int i=t;i<256;i+=128){
            int r=i>>6, xx=i&63, yy=y0-1+r;
            xs[0][r][xx] = (yy>=0&&yy<64)? xb[(yy<<6)+xx] : 0.f;
        }
        __syncthreads();
        for (int c=0;c<64;c++){
            if (c+1<64){
                const float* xp = xb + ((size_t)(c+1)<<12);
                #pragma unroll
                for (int i=t;i<256;i+=128){
                    int r=i>>6, xx=i&63, yy=y0-1+r;
                    xs[(c+1)&1][r][xx] = (yy>=0&&yy<64)? xp[(yy<<6)+xx] : 0.f;
                }
            }
            const float (*cur)[64] = xs[c&1];
            float v[3][3];
            #pragma unroll
            for (int dy=0;dy<3;dy++)
                #pragma unroll
                for (int dx=-1;dx<=1;dx++){
                    int xx=tx+dx;
                    v[dy][dx+1] = (xx>=0&&xx<64)? cur[ty+dy][xx] : 0.f;
                }
            float gx = (v[0][2]+2.f*v[1][2]+v[2][2]) - (v[0][0]+2.f*v[1][0]+v[2][0]);
            float gy = (v[2][0]+2.f*v[2][1]+v[2][2]) - (v[0][0]+2.f*v[0][1]+v[0][2]);
            ssum += sqrtf(gx*gx+gy*gy);
            float ctr = v[1][1];
            csum += ctr; mx = fmaxf(mx,ctr); mn = fminf(mn,ctr);
            __syncthreads();
        }
        int id = (b<<12) + (y<<6) + tx;
        g_sobel[id] = sigmoidf_(ssum*(1.0f/64.0f));
        g_hsv[id]   = (mx-mn+1e-6f)/(mx+1e-6f);
        g_hist[id]  = sigmoidf_(csum*(1.0f/64.0f));
    } else {
        // ---- fftB: wait for branch flag, then col DFT + mag (gated)
        const int e = blk - 1792;
        const int uh = e&1, c = (e>>1)&63, b = e>>7;
        if (t==0){
            while (atomicAdd(&g_flag, 0) == 0) __nanosleep(200);
        }
        __syncthreads();
        __threadfence();
        volatile int* vbr = g_branch;
        if (vbr[b] != 3) return;
        float* Rs = (float*)sm8;            // NV*65
        float* Is = Rs + NV*65;
        const size_t base = (size_t)((b<<6)+c)*NV*64;
        for (int i=t;i<NV*64;i+=128){
            int v=i>>6, r=i&63;
            Rs[v*65+r] = g_fre[base+i];
            Is[v*65+r] = g_fim[base+i];
        }
        __syncthreads();
        float* outp = g_fftmag + ((size_t)(((b<<6)+c))<<12);
        for (int i=t;i<32*NV;i+=128){
            int u = uh*32 + i/NV, v = i - (i/NV)*NV;
            float st, ct;
            __sincosf(-6.283185307179586f*(float)u*(1.0f/64.0f), &st, &ct);
            float cu=1.f, su=0.f, fr=0.f, fi=0.f;
            const float* Rp = Rs + v*65;
            const float* Ip = Is + v*65;
            #pragma unroll 4
            for (int r=0;r<64;r++){
                float a=Rp[r], bm=Ip[r];
                fr += a*cu - bm*su;
                fi += a*su + bm*cu;
                float cn = cu*ct - su*st;
                su = su*ct + cu*st;
                cu = cn;
                if ((r&15)==15){
                    float nrm = __frsqrt_rn(cu*cu + su*su);
                    cu *= nrm; su *= nrm;
                }
            }
            float mag = sqrtf(fr*fr+fi*fi);
            int su_=(u+32)&63, sv_=(v+32)&63;
            outp[(su_<<6)+sv_] = mag;
            int u2=(64-u)&63, v2=(64-v)&63;
            int su2=(u2+32)&63, sv2=(v2+32)&63;
            outp[(su2<<6)+sv2] = mag;
        }
    }
}

// ---------------- combine split partials + routed spatial epilogue ----------------
// grid (256, 4): blk.x = (ntile 0..63, cgroup 0..3); 16 channels x 64 q per block
__global__ void __launch_bounds__(256) attn_finish(const float* __restrict__ x,
                                                   const float* __restrict__ swp,
                                                   float* __restrict__ out){
    __shared__ float scl[64];
    const int t = threadIdx.x;
    const int bx = blockIdx.x;
    const int ntile = bx & 63, cg = bx >> 6;
    const int b = blockIdx.y, n0 = ntile*64;
    if (bx==0 && b==0 && t==0){   // reset for next graph replay
        g_cnt = 0; g_flag = 0; g_m_cnt = 0; g_m_flag = 0;
    }
    if (t < 64){
        float d = 0.f;
        #pragma unroll
        for (int s=0;s<NSPL;s++) d += g_dpart[((s*BB + b)<<12) + n0 + t];
        const int br = g_branch[b];
        const int id = (b<<12) + n0 + t;
        float v;
        if      (br==0) v = g_sobel[id];
        else if (br==1) v = g_hsv[id];
        else if (br==2) v = g_hist[id];
        else {
            float s=0.f;
            const float* mp = g_fftmag + ((size_t)b<<18) + n0 + t;
            #pragma unroll 4
            for (int c=0;c<64;c++) s += mp[(size_t)c<<12];
            v = sigmoidf_(s*(1.0f/64.0f));
        }
        scl[t] = swp[0]*v/d;
    }
    __syncthreads();
    for (int i=t;i<1024;i+=256){
        int c = cg*16 + (i>>6), q = i&63;
        size_t po = ((size_t)(b*CC + c)<<12) + n0 + q;
        float osum = 0.f;
        #pragma unroll
        for (int s=0;s<NSPL;s++) osum += g_Opart[((size_t)(s*BB*CC)<<12) + po];
        out[po] = osum*scl[q] + x[po];
    }
}

// ---------------- launch ----------------
extern "C" void kernel_launch(void* const* d_in, const int* in_sizes, int n_in,
                              void* d_out, int out_size){
    const float* x    = (const float*)d_in[0];
    const float* wq   = (const float*)d_in[1];
    const float* bq   = (const float*)d_in[2];
    const float* wk   = (const float*)d_in[3];
    const float* bk   = (const float*)d_in[4];
    const float* wv   = (const float*)d_in[5];
    const float* bv   = (const float*)d_in[6];
    const float* c1w  = (const float*)d_in[7];
    const float* c1b  = (const float*)d_in[8];
    const float* c2w  = (const float*)d_in[9];
    const float* c2b  = (const float*)d_in[10];
    const float* fcw  = (const float*)d_in[11];
    const float* fcb  = (const float*)d_in[12];
    const float* swp  = (const float*)d_in[13];
    float* out = (float*)d_out;

    cudaFuncSetAttribute(phase1_kernel, cudaFuncAttributeMaxDynamicSharedMemorySize, 21504);

    phase1_kernel  <<<1024, 256, 21504>>>(x, wq,bq, wk,bk, wv,bv, c1w, c1b);
    phase2_kernel  <<<2304, 128, 19584>>>(x, c2w, c2b, fcw, fcb);
    attn_finish    <<<dim3(256,4), 256>>>(x, swp, out);
}